// round 4
// baseline (speedup 1.0000x reference)
#include <cuda_runtime.h>

// Problem constants: B=64, S=1024, D=64, U=128, NB=8, SIG_DIM=4160
// Final-KAN feature length: 64 (silu) + 64*8 (spline) = 576

__device__ float d_sig[64 * 4160];
__device__ float d_h1[64 * 128];
__device__ float d_skip[64 * 128];
__device__ float d_wts[64 * 128];

__device__ __forceinline__ float siluf(float v) { return v / (1.f + __expf(-v)); }
__device__ __forceinline__ float sigmf(float v) { return 1.f / (1.f + __expf(-v)); }

// Cox-de Boor, GRID_SIZE=5, order 3, uniform knots g(k)=0.4k-2.2, k=0..11 -> 8 bases
__device__ __forceinline__ void bspline8(float x, float* o) {
    float bb[11];
#pragma unroll
    for (int k = 0; k < 11; k++) {
        float gk  = 0.4f * k - 2.2f;
        float gk1 = 0.4f * (k + 1) - 2.2f;
        bb[k] = (x >= gk && x < gk1) ? 1.f : 0.f;
    }
#pragma unroll
    for (int p = 1; p <= 3; p++) {
        float inv = 1.f / (0.4f * p);
#pragma unroll
        for (int k = 0; k + p < 11; k++) {
            float gk   = 0.4f * k - 2.2f;
            float gkp1 = 0.4f * (k + p + 1) - 2.2f;
            bb[k] = (x - gk) * inv * bb[k] + (gkp1 - x) * inv * bb[k + 1];
        }
    }
#pragma unroll
    for (int k = 0; k < 8; k++) o[k] = bb[k];
}

// ---- packed f32x2 helpers ----
__device__ __forceinline__ void ffma2(unsigned long long& d, unsigned long long a,
                                      unsigned long long b) {
    asm("fma.rn.f32x2 %0, %1, %2, %0;" : "+l"(d) : "l"(a), "l"(b));
}
__device__ __forceinline__ unsigned long long bcast2(float v) {
    unsigned long long r; unsigned int u = __float_as_uint(v);
    asm("mov.b64 %0, {%1, %1};" : "=l"(r) : "r"(u));
    return r;
}
__device__ __forceinline__ float2 unpack2(unsigned long long v) {
    unsigned int lo, hi;
    asm("mov.b64 {%0, %1}, %2;" : "=r"(lo), "=r"(hi) : "l"(v));
    return make_float2(__uint_as_float(lo), __uint_as_float(hi));
}

// ============ K0: init — S1 = w[S-1]-w[0]; zero S2 / h1 / skip ============
__global__ void k_init(const float* __restrict__ x, const float* __restrict__ tw) {
    int idx = blockIdx.x * blockDim.x + threadIdx.x;
    if (idx < 64 * 4160) {
        int b = idx / 4160, r = idx - b * 4160;
        if (r < 64) {
            float wl = tw[1023] * x[((size_t)b * 1024 + 1023) * 64 + r];
            float w0 = tw[0]    * x[(size_t)b * 1024 * 64 + r];
            d_sig[idx] = wl - w0;
        } else {
            d_sig[idx] = 0.f;
        }
    }
    if (idx < 64 * 128) { d_h1[idx] = 0.f; d_skip[idx] = 0.f; }
}

// ============ K1: level-2 signature. Stage M/U for whole chunk, then barrier-free
// FFMA2 outer product. S2[i][j] = sum_t (0.5(w_t+w_{t+1})-w_0)_i (w_{t+1}-w_t)_j ====
#define KSIG_SMEM (2 * 128 * 64 * 4)
__global__ __launch_bounds__(256) void k_sig(const float* __restrict__ x,
                                             const float* __restrict__ tw) {
    extern __shared__ float sm[];
    float* sM = sm;                 // [128][64]
    float* sU = sm + 128 * 64;      // [128][64]
    const int b = blockIdx.x;
    const int chunk = blockIdx.y;
    const int t0 = chunk * 128;
    const int steps = (chunk == 7) ? 127 : 128;   // 1023 increments total
    const int tid = threadIdx.x;
    const size_t xb = (size_t)b * 1024 * 64;
    for (int e = tid; e < steps * 64; e += 256) {
        int t = e >> 6, d = e & 63;
        float wt0 = tw[t0 + t]     * x[xb + (size_t)(t0 + t) * 64 + d];
        float wt1 = tw[t0 + t + 1] * x[xb + (size_t)(t0 + t + 1) * 64 + d];
        float w0v = tw[0] * x[xb + d];
        sU[t * 64 + d] = wt1 - wt0;
        sM[t * 64 + d] = 0.5f * (wt0 + wt1) - w0v;
    }
    __syncthreads();
    const int jp = tid & 31;        // j pair (2jp, 2jp+1)
    const int i0 = (tid >> 5) * 8;  // 8 i values
    unsigned long long acc[8];
#pragma unroll
    for (int q = 0; q < 8; q++) acc[q] = 0ull;
#pragma unroll 2
    for (int t = 0; t < steps; t++) {
        const float4 m0 = *reinterpret_cast<const float4*>(&sM[t * 64 + i0]);
        const float4 m1 = *reinterpret_cast<const float4*>(&sM[t * 64 + i0 + 4]);
        const unsigned long long u2 =
            *reinterpret_cast<const unsigned long long*>(&sU[t * 64 + 2 * jp]);
        ffma2(acc[0], u2, bcast2(m0.x));
        ffma2(acc[1], u2, bcast2(m0.y));
        ffma2(acc[2], u2, bcast2(m0.z));
        ffma2(acc[3], u2, bcast2(m0.w));
        ffma2(acc[4], u2, bcast2(m1.x));
        ffma2(acc[5], u2, bcast2(m1.y));
        ffma2(acc[6], u2, bcast2(m1.z));
        ffma2(acc[7], u2, bcast2(m1.w));
    }
#pragma unroll
    for (int q = 0; q < 8; q++) {
        float2 f = unpack2(acc[q]);
        int i = i0 + q;
        atomicAdd(&d_sig[b * 4160 + 64 + i * 64 + 2 * jp],     f.x);
        atomicAdd(&d_sig[b * 4160 + 64 + i * 64 + 2 * jp + 1], f.y);
    }
}

// ============ K2: GRKAN layer 1 (h1) + skip, split-K over 65 chunks, atomics ======
#define K3_SMEM ((4096 + 4096 + 32768) * 4)
__global__ __launch_bounds__(256, 1) void k_grkan1(const float* __restrict__ g1_base,
                                                   const float* __restrict__ g1_spline,
                                                   const float* __restrict__ skip_w) {
    extern __shared__ float sm[];
    float* s_sig = sm;          // [64 b][64 d]
    float* s_sil = sm + 4096;
    float* s_bas = sm + 8192;   // [64][64][8]
    const int ct = blockIdx.x, kc = blockIdx.y;
    const int d0 = kc * 64;
    const int tid = threadIdx.x;
    for (int e = tid; e < 4096; e += 256) {
        int bidx = e >> 6, dl = e & 63;
        float v = d_sig[bidx * 4160 + d0 + dl];
        s_sig[e] = v;
        s_sil[e] = siluf(v);
        bspline8(v, &s_bas[e * 8]);
    }
    __syncthreads();
    const int col = ct * 32 + (tid & 31);
    const int ty  = tid >> 5;
    float acc_h[8], acc_s[8];
#pragma unroll
    for (int r = 0; r < 8; r++) { acc_h[r] = 0.f; acc_s[r] = 0.f; }
    for (int dl = 0; dl < 64; dl++) {
        const int d = d0 + dl;
        float wb = g1_base[d * 128 + col];
        float wk = skip_w[d * 128 + col];
        float ws[8];
#pragma unroll
        for (int nb = 0; nb < 8; nb++) ws[nb] = g1_spline[((size_t)d * 8 + nb) * 128 + col];
#pragma unroll
        for (int r = 0; r < 8; r++) {
            int bidx = ty * 8 + r;
            const float* bp = &s_bas[(bidx * 64 + dl) * 8];
            float h = s_sil[bidx * 64 + dl] * wb;
#pragma unroll
            for (int nb = 0; nb < 8; nb++) h += bp[nb] * ws[nb];
            acc_h[r] += h;
            acc_s[r] += s_sig[bidx * 64 + dl] * wk;
        }
    }
#pragma unroll
    for (int r = 0; r < 8; r++) {
        int bidx = ty * 8 + r;
        atomicAdd(&d_h1[bidx * 128 + col], acc_h[r]);
        atomicAdd(&d_skip[bidx * 128 + col], acc_s[r]);
    }
}

// ============ K3: GRKAN layer 2 + gate + layernorm + softmax -> d_wts ============
// 64 blocks (1 batch each) x 256 threads, split-K x2 inside the block.
__device__ __forceinline__ float bsum256(float v, volatile float* red) {
#pragma unroll
    for (int o = 16; o > 0; o >>= 1) v += __shfl_xor_sync(0xffffffffu, v, o);
    int w = threadIdx.x >> 5;
    __syncthreads();
    if ((threadIdx.x & 31) == 0) red[w] = v;
    __syncthreads();
    float s = 0.f;
#pragma unroll
    for (int i = 0; i < 8; i++) s += red[i];
    return s;
}
__device__ __forceinline__ float bmax256(float v, volatile float* red) {
#pragma unroll
    for (int o = 16; o > 0; o >>= 1) v = fmaxf(v, __shfl_xor_sync(0xffffffffu, v, o));
    int w = threadIdx.x >> 5;
    __syncthreads();
    if ((threadIdx.x & 31) == 0) red[w] = v;
    __syncthreads();
    float s = red[0];
#pragma unroll
    for (int i = 1; i < 8; i++) s = fmaxf(s, red[i]);
    return s;
}

__global__ __launch_bounds__(256) void k_grkan2(
    const float* __restrict__ g2_base, const float* __restrict__ g2_spline,
    const float* __restrict__ skip_b,
    const float* __restrict__ gate_ws, const float* __restrict__ gate_bs,
    const float* __restrict__ gate_wv, const float* __restrict__ gate_bv,
    const float* __restrict__ ln_g, const float* __restrict__ ln_b) {
    __shared__ float s_sil[128];
    __shared__ float s_bas[128][8];
    __shared__ float s_h2[128];
    __shared__ float s_pa[128], s_pv[128];
    __shared__ float red[8];
    const int b = blockIdx.x;
    const int tid = threadIdx.x;
    const int u = tid & 127;
    const int kh = tid >> 7;          // 0/1 : k-half
    if (tid < 128) {
        float v = d_h1[b * 128 + tid];
        s_sil[tid] = siluf(v);
        bspline8(v, &s_bas[tid][0]);
    }
    __syncthreads();
    // h2 = kan_linear(h1, g2)
    float acc = 0.f;
    const int kb = kh * 64;
#pragma unroll 4
    for (int kk = 0; kk < 64; kk++) {
        int k = kb + kk;
        float h = s_sil[k] * g2_base[k * 128 + u];
#pragma unroll
        for (int nb = 0; nb < 8; nb++)
            h += s_bas[k][nb] * g2_spline[((size_t)k * 8 + nb) * 128 + u];
        acc += h;
    }
    if (kh == 1) s_pa[u] = acc;
    __syncthreads();
    if (kh == 0) s_h2[u] = acc + s_pa[u];
    __syncthreads();
    // gate GEMMs
    float sa = 0.f, va = 0.f;
#pragma unroll 4
    for (int kk = 0; kk < 64; kk++) {
        int k = kb + kk;
        float h = s_h2[k];
        sa += h * gate_ws[k * 128 + u];
        va += h * gate_wv[k * 128 + u];
    }
    if (kh == 1) { s_pa[u] = sa; s_pv[u] = va; }
    __syncthreads();
    float y = 0.f;
    if (kh == 0) {
        sa += s_pa[u]; va += s_pv[u];
        float gate = sigmf(sa + gate_bs[u]) * (va + gate_bv[u]);
        y = d_skip[b * 128 + u] + skip_b[u] + gate;
    }
    // LN + softmax over 128 (all 256 threads join reductions; kh==1 contributes 0)
    float v = (kh == 0) ? y : 0.f;
    float mu = bsum256(v, red) * (1.f / 128.f);
    float dv = (kh == 0) ? (v - mu) : 0.f;
    float var = bsum256(dv * dv, red) * (1.f / 128.f);
    float z = (kh == 0) ? (ln_g[u] * dv / sqrtf(var + 1e-3f) + ln_b[u]) : -1e30f;
    float mx = bmax256(z, red);
    float ez = (kh == 0) ? __expf(z - mx) : 0.f;
    float es = bsum256(ez, red);
    if (kh == 0) d_wts[b * 128 + u] = ez / es;
}

// ============ K4: final KAN — (65536 x 576) @ (576 x 128), scaled by d_wts ========
// 444 blocks (= 3*148). Per block: one 64-col half, loop over 32-row subtiles.
// Thread: 8 rows x 2 cols (16 fp32 MACs via 8 FFMA2 per k). K split across two
// warp-groups (288 k each), partials reduced via smem (reusing A region).
#define K5_SMEM ((576 * 64 + 576 * 36) * 4)
__global__ __launch_bounds__(256, 1) void k_main(const float* __restrict__ x,
                                                 const float* __restrict__ tw,
                                                 const float* __restrict__ kan_base,
                                                 const float* __restrict__ kan_spline,
                                                 float* __restrict__ out) {
    extern __shared__ float sm[];
    float* Wlo = sm;                 // [576][32] cols half*64 + 0..31
    float* Whi = sm + 576 * 32;      // [576][32] cols half*64 + 32..63
    float* A   = sm + 576 * 64;      // [576][36] feature tile (also partials buffer)
    const int half = blockIdx.x & 1;
    const int bseq = blockIdx.x >> 1;   // 0..221
    const int tid = threadIdx.x;
    const int c0 = half * 64;
    for (int e = tid; e < 576 * 32; e += 256) {
        int k = e >> 5, p = e & 31;
        Wlo[e] = (k < 64) ? kan_base[k * 128 + c0 + p]
                          : kan_spline[(size_t)(k - 64) * 128 + c0 + p];
        Whi[e] = (k < 64) ? kan_base[k * 128 + c0 + 32 + p]
                          : kan_spline[(size_t)(k - 64) * 128 + c0 + 32 + p];
    }
    const int p   = tid & 31;
    const int wid = tid >> 5;
    const int g   = wid >> 2;          // k-group
    const int wg  = wid & 3;           // rowgroup -> rows r0..r0+7
    const int r0  = wg * 8;
    const int kbeg = g * 288, kend = kbeg + 288;
    __syncthreads();

    for (int s = bseq; s < 2048; s += 222) {   // 2048 subtiles of 32 rows per half
        const int r0g = s * 32;
        const int b   = r0g >> 10;
        // ---- build feature tile A (all 256 threads) ----
        {
            const int r  = tid & 31;
            const int wq = tid >> 5;
            const int gr = r0g + r;
            const float t = tw[gr & 1023];
            const float4 xa = *reinterpret_cast<const float4*>(&x[(size_t)gr * 64 + wq * 4]);
            const float4 xb = *reinterpret_cast<const float4*>(&x[(size_t)gr * 64 + wq * 4 + 32]);
            float xv[8] = {xa.x, xa.y, xa.z, xa.w, xb.x, xb.y, xb.z, xb.w};
#pragma unroll
            for (int i = 0; i < 8; i++) {
                int d = wq * 4 + (i & 3) + (i >> 2) * 32;
                float w = t * xv[i];
                A[d * 36 + r] = siluf(w);
                float bas[8];
                bspline8(w, bas);
#pragma unroll
                for (int nb = 0; nb < 8; nb++) A[(64 + d * 8 + nb) * 36 + r] = bas[nb];
            }
        }
        __syncthreads();
        // ---- GEMM over this group's K range ----
        unsigned long long a[8];
#pragma unroll
        for (int q = 0; q < 8; q++) a[q] = 0ull;
#pragma unroll 4
        for (int k = kbeg; k < kend; k++) {
            const unsigned long long bl = bcast2(Wlo[k * 32 + p]);
            const unsigned long long bh = bcast2(Whi[k * 32 + p]);
            const float* ap = &A[k * 36 + r0];
            const ulonglong2 v0 = *reinterpret_cast<const ulonglong2*>(ap);
            const ulonglong2 v1 = *reinterpret_cast<const ulonglong2*>(ap + 4);
            ffma2(a[0], v0.x, bl); ffma2(a[1], v0.y, bl);
            ffma2(a[2], v1.x, bl); ffma2(a[3], v1.y, bl);
            ffma2(a[4], v0.x, bh); ffma2(a[5], v0.y, bh);
            ffma2(a[6], v1.x, bh); ffma2(a[7], v1.y, bh);
        }
        __syncthreads();           // everyone done reading A
        unsigned long long* P = reinterpret_cast<unsigned long long*>(A);
        if (g == 1) {
            const int base = (wg * 32 + p) * 9;
#pragma unroll
            for (int q = 0; q < 8; q++) P[base + q] = a[q];
        }
        __syncthreads();
        if (g == 0) {
            const float wt0 = d_wts[b * 128 + c0 + p];
            const float wt1 = d_wts[b * 128 + c0 + 32 + p];
            const int base = (wg * 32 + p) * 9;
            size_t ob = (size_t)(r0g + r0) * 128 + c0 + p;
#pragma unroll
            for (int q = 0; q < 4; q++) {
                float2 s0 = unpack2(a[q]),     p0 = unpack2(P[base + q]);
                float2 s1 = unpack2(a[4 + q]), p1 = unpack2(P[base + 4 + q]);
                out[ob + (size_t)(2 * q) * 128]          = (s0.x + p0.x) * wt0;
                out[ob + (size_t)(2 * q + 1) * 128]      = (s0.y + p0.y) * wt0;
                out[ob + (size_t)(2 * q) * 128 + 32]     = (s1.x + p1.x) * wt1;
                out[ob + (size_t)(2 * q + 1) * 128 + 32] = (s1.y + p1.y) * wt1;
            }
        }
        __syncthreads();           // before next sub overwrites A/P
    }
}

extern "C" void kernel_launch(void* const* d_in, const int* in_sizes, int n_in,
                              void* d_out, int out_size) {
    const float* x          = (const float*)d_in[0];
    const float* tw         = (const float*)d_in[1];
    const float* kan_base   = (const float*)d_in[2];
    const float* kan_spline = (const float*)d_in[3];
    const float* g1_base    = (const float*)d_in[4];
    const float* g1_spline  = (const float*)d_in[5];
    const float* g2_base    = (const float*)d_in[6];
    const float* g2_spline  = (const float*)d_in[7];
    const float* skip_w     = (const float*)d_in[8];
    const float* skip_b     = (const float*)d_in[9];
    const float* gate_ws    = (const float*)d_in[10];
    const float* gate_bs    = (const float*)d_in[11];
    const float* gate_wv    = (const float*)d_in[12];
    const float* gate_bv    = (const float*)d_in[13];
    const float* ln_g       = (const float*)d_in[14];
    const float* ln_b       = (const float*)d_in[15];
    float* out = (float*)d_out;

    cudaFuncSetAttribute(k_sig,    cudaFuncAttributeMaxDynamicSharedMemorySize, KSIG_SMEM);
    cudaFuncSetAttribute(k_grkan1, cudaFuncAttributeMaxDynamicSharedMemorySize, K3_SMEM);
    cudaFuncSetAttribute(k_main,   cudaFuncAttributeMaxDynamicSharedMemorySize, K5_SMEM);

    k_init<<<(64 * 4160 + 255) / 256, 256>>>(x, tw);
    k_sig<<<dim3(64, 8), 256, KSIG_SMEM>>>(x, tw);
    k_grkan1<<<dim3(4, 65), 256, K3_SMEM>>>(g1_base, g1_spline, skip_w);
    k_grkan2<<<64, 256>>>(g2_base, g2_spline, skip_b, gate_ws, gate_bs,
                          gate_wv, gate_bv, ln_g, ln_b);
    k_main<<<444, 256, K5_SMEM>>>(x, tw, kan_base, kan_spline, out);
}

// round 8
// speedup vs baseline: 2.3115x; 2.3115x over previous
#include <cuda_runtime.h>
#include <cuda_bf16.h>
#include <cstdint>

// B=64, S=1024, D=64, U=128, NB=8, SIG_DIM=4160; final-KAN K = 64+512 = 576
// K = 36 ksteps of 16; N = 128 = 16 n-frags of 8.

__device__ float d_sig[64 * 4160];
__device__ float d_h1[64 * 128];
__device__ float d_h2g[64 * 128];
__device__ float d_skip[64 * 128];
__device__ float d_wts[64 * 128];
// B operand in m16n8k16 fragment layout: [kstep 36][nfrag 16][lane 32] = {bh0,bh1,bl0,bl1}
__device__ uint4 d_Bfrag[36 * 16 * 32];

__device__ __forceinline__ float siluf(float v) { return v / (1.f + __expf(-v)); }
__device__ __forceinline__ float sigmf(float v) { return 1.f / (1.f + __expf(-v)); }

// Cox-de Boor, GRID_SIZE=5, order 3, uniform knots g(k)=0.4k-2.2 -> 8 bases
__device__ __forceinline__ void bspline8(float x, float* o) {
    float bb[11];
#pragma unroll
    for (int k = 0; k < 11; k++) {
        float gk = 0.4f * k - 2.2f, gk1 = 0.4f * (k + 1) - 2.2f;
        bb[k] = (x >= gk && x < gk1) ? 1.f : 0.f;
    }
#pragma unroll
    for (int p = 1; p <= 3; p++) {
        float inv = 1.f / (0.4f * p);
#pragma unroll
        for (int k = 0; k + p < 11; k++) {
            float gk = 0.4f * k - 2.2f, gkp1 = 0.4f * (k + p + 1) - 2.2f;
            bb[k] = (x - gk) * inv * bb[k] + (gkp1 - x) * inv * bb[k + 1];
        }
    }
#pragma unroll
    for (int k = 0; k < 8; k++) o[k] = bb[k];
}

__device__ __forceinline__ void ffma2(unsigned long long& d, unsigned long long a,
                                      unsigned long long b) {
    asm("fma.rn.f32x2 %0, %1, %2, %0;" : "+l"(d) : "l"(a), "l"(b));
}
__device__ __forceinline__ unsigned long long bcast2(float v) {
    unsigned long long r; unsigned int u = __float_as_uint(v);
    asm("mov.b64 %0, {%1, %1};" : "=l"(r) : "r"(u));
    return r;
}
__device__ __forceinline__ float2 unpack2(unsigned long long v) {
    unsigned int lo, hi;
    asm("mov.b64 {%0, %1}, %2;" : "=r"(lo), "=r"(hi) : "l"(v));
    return make_float2(__uint_as_float(lo), __uint_as_float(hi));
}
// split fp32 pair -> packed bf16 hi pair + bf16 lo (residual) pair
__device__ __forceinline__ void split2(float a, float b, uint32_t& h, uint32_t& l) {
    __nv_bfloat16 ah = __float2bfloat16(a), bh = __float2bfloat16(b);
    __nv_bfloat16 al = __float2bfloat16(a - __bfloat162float(ah));
    __nv_bfloat16 bl = __float2bfloat16(b - __bfloat162float(bh));
    h = (uint32_t)__bfloat16_as_ushort(ah) | ((uint32_t)__bfloat16_as_ushort(bh) << 16);
    l = (uint32_t)__bfloat16_as_ushort(al) | ((uint32_t)__bfloat16_as_ushort(bl) << 16);
}
// m16n8k16 row.col bf16 MMA, fp32 accumulate in place
__device__ __forceinline__ void mma16816(float* d, uint32_t a0, uint32_t a1, uint32_t a2,
                                         uint32_t a3, uint32_t b0, uint32_t b1) {
    asm("mma.sync.aligned.m16n8k16.row.col.f32.bf16.bf16.f32 "
        "{%0,%1,%2,%3}, {%4,%5,%6,%7}, {%8,%9}, {%0,%1,%2,%3};"
        : "+f"(d[0]), "+f"(d[1]), "+f"(d[2]), "+f"(d[3])
        : "r"(a0), "r"(a1), "r"(a2), "r"(a3), "r"(b0), "r"(b1));
}

// ============ K0: init ============
__global__ void k_init(const float* __restrict__ x, const float* __restrict__ tw) {
    int idx = blockIdx.x * blockDim.x + threadIdx.x;
    if (idx < 64 * 4160) {
        int b = idx / 4160, r = idx - b * 4160;
        if (r < 64) {
            float wl = tw[1023] * x[((size_t)b * 1024 + 1023) * 64 + r];
            float w0 = tw[0]    * x[(size_t)b * 1024 * 64 + r];
            d_sig[idx] = wl - w0;
        } else d_sig[idx] = 0.f;
    }
    if (idx < 64 * 128) { d_h1[idx] = 0.f; d_skip[idx] = 0.f; d_h2g[idx] = 0.f; }
}

// ============ K-prep: W^T (576x128) -> bf16 hi/lo m16n8k16 B-fragment layout ======
// lane l of frag (s,f): b0={B[k0][n],B[k0+1][n]}, b1={B[k0+8][n],B[k0+9][n]},
// k0 = s*16+(l%4)*2, n = f*8 + l/4.
__global__ void k_prep(const float* __restrict__ kan_base,
                       const float* __restrict__ kan_spline) {
    int idx = blockIdx.x * blockDim.x + threadIdx.x;
    if (idx >= 36 * 16 * 32) return;
    int l = idx & 31, f = (idx >> 5) & 15, s = idx >> 9;
    int n = f * 8 + (l >> 2);
    int k0 = s * 16 + (l & 3) * 2;
    float w[4];
#pragma unroll
    for (int q = 0; q < 4; q++) {
        int k = k0 + (q >> 1) * 8 + (q & 1);
        w[q] = (k < 64) ? kan_base[k * 128 + n] : kan_spline[(size_t)(k - 64) * 128 + n];
    }
    uint4 v;
    split2(w[0], w[1], v.x, v.z);
    split2(w[2], w[3], v.y, v.w);
    d_Bfrag[idx] = v;
}

// ============ K1: level-2 signature (unchanged) ============
#define KSIG_SMEM (2 * 128 * 64 * 4)
__global__ __launch_bounds__(256) void k_sig(const float* __restrict__ x,
                                             const float* __restrict__ tw) {
    extern __shared__ float sm[];
    float* sM = sm; float* sU = sm + 128 * 64;
    const int b = blockIdx.x, chunk = blockIdx.y, t0 = chunk * 128;
    const int steps = (chunk == 7) ? 127 : 128;
    const int tid = threadIdx.x;
    const size_t xb = (size_t)b * 1024 * 64;
    for (int e = tid; e < steps * 64; e += 256) {
        int t = e >> 6, d = e & 63;
        float wt0 = tw[t0 + t]     * x[xb + (size_t)(t0 + t) * 64 + d];
        float wt1 = tw[t0 + t + 1] * x[xb + (size_t)(t0 + t + 1) * 64 + d];
        float w0v = tw[0] * x[xb + d];
        sU[t * 64 + d] = wt1 - wt0;
        sM[t * 64 + d] = 0.5f * (wt0 + wt1) - w0v;
    }
    __syncthreads();
    const int jp = tid & 31, i0 = (tid >> 5) * 8;
    unsigned long long acc[8];
#pragma unroll
    for (int q = 0; q < 8; q++) acc[q] = 0ull;
#pragma unroll 2
    for (int t = 0; t < steps; t++) {
        const float4 m0 = *reinterpret_cast<const float4*>(&sM[t * 64 + i0]);
        const float4 m1 = *reinterpret_cast<const float4*>(&sM[t * 64 + i0 + 4]);
        const unsigned long long u2 =
            *reinterpret_cast<const unsigned long long*>(&sU[t * 64 + 2 * jp]);
        ffma2(acc[0], u2, bcast2(m0.x)); ffma2(acc[1], u2, bcast2(m0.y));
        ffma2(acc[2], u2, bcast2(m0.z)); ffma2(acc[3], u2, bcast2(m0.w));
        ffma2(acc[4], u2, bcast2(m1.x)); ffma2(acc[5], u2, bcast2(m1.y));
        ffma2(acc[6], u2, bcast2(m1.z)); ffma2(acc[7], u2, bcast2(m1.w));
    }
#pragma unroll
    for (int q = 0; q < 8; q++) {
        float2 f = unpack2(acc[q]);
        int i = i0 + q;
        atomicAdd(&d_sig[b * 4160 + 64 + i * 64 + 2 * jp],     f.x);
        atomicAdd(&d_sig[b * 4160 + 64 + i * 64 + 2 * jp + 1], f.y);
    }
}

// ============ K2: GRKAN layer 1 + skip (unchanged) ============
#define K3_SMEM ((4096 + 4096 + 32768) * 4)
__global__ __launch_bounds__(256, 1) void k_grkan1(const float* __restrict__ g1_base,
                                                   const float* __restrict__ g1_spline,
                                                   const float* __restrict__ skip_w) {
    extern __shared__ float sm[];
    float* s_sig = sm; float* s_sil = sm + 4096; float* s_bas = sm + 8192;
    const int ct = blockIdx.x, kc = blockIdx.y, d0 = kc * 64, tid = threadIdx.x;
    for (int e = tid; e < 4096; e += 256) {
        int bidx = e >> 6, dl = e & 63;
        float v = d_sig[bidx * 4160 + d0 + dl];
        s_sig[e] = v; s_sil[e] = siluf(v);
        bspline8(v, &s_bas[e * 8]);
    }
    __syncthreads();
    const int col = ct * 32 + (tid & 31), ty = tid >> 5;
    float acc_h[8], acc_s[8];
#pragma unroll
    for (int r = 0; r < 8; r++) { acc_h[r] = 0.f; acc_s[r] = 0.f; }
    for (int dl = 0; dl < 64; dl++) {
        const int d = d0 + dl;
        float wb = g1_base[d * 128 + col], wk = skip_w[d * 128 + col];
        float ws[8];
#pragma unroll
        for (int nb = 0; nb < 8; nb++) ws[nb] = g1_spline[((size_t)d * 8 + nb) * 128 + col];
#pragma unroll
        for (int r = 0; r < 8; r++) {
            int bidx = ty * 8 + r;
            const float* bp = &s_bas[(bidx * 64 + dl) * 8];
            float h = s_sil[bidx * 64 + dl] * wb;
#pragma unroll
            for (int nb = 0; nb < 8; nb++) h += bp[nb] * ws[nb];
            acc_h[r] += h;
            acc_s[r] += s_sig[bidx * 64 + dl] * wk;
        }
    }
#pragma unroll
    for (int r = 0; r < 8; r++) {
        int bidx = ty * 8 + r;
        atomicAdd(&d_h1[bidx * 128 + col], acc_h[r]);
        atomicAdd(&d_skip[bidx * 128 + col], acc_s[r]);
    }
}

// ============ K3a: h2 = kan_linear(h1, g2), split-K x4, 256 blocks ============
__global__ __launch_bounds__(128) void k_grkan2a(const float* __restrict__ g2_base,
                                                 const float* __restrict__ g2_spline) {
    __shared__ float s_sil[32];
    __shared__ float s_bas[32][8];
    const int b = blockIdx.x >> 2, kq = blockIdx.x & 3;
    const int u = threadIdx.x;
    const int k0 = kq * 32;
    if (u < 32) {
        float v = d_h1[b * 128 + k0 + u];
        s_sil[u] = siluf(v);
        bspline8(v, &s_bas[u][0]);
    }
    __syncthreads();
    float acc = 0.f;
#pragma unroll 8
    for (int kk = 0; kk < 32; kk++) {
        int k = k0 + kk;
        float h = s_sil[kk] * g2_base[k * 128 + u];
#pragma unroll
        for (int nb = 0; nb < 8; nb++)
            h += s_bas[kk][nb] * g2_spline[((size_t)k * 8 + nb) * 128 + u];
        acc += h;
    }
    atomicAdd(&d_h2g[b * 128 + u], acc);
}

// ============ K3b: gate + layernorm + softmax -> d_wts (64 blocks x 128) ============
__device__ __forceinline__ float bsum128(float v, volatile float* red) {
#pragma unroll
    for (int o = 16; o > 0; o >>= 1) v += __shfl_xor_sync(0xffffffffu, v, o);
    int w = threadIdx.x >> 5;
    __syncthreads();
    if ((threadIdx.x & 31) == 0) red[w] = v;
    __syncthreads();
    return red[0] + red[1] + red[2] + red[3];
}
__device__ __forceinline__ float bmax128(float v, volatile float* red) {
#pragma unroll
    for (int o = 16; o > 0; o >>= 1) v = fmaxf(v, __shfl_xor_sync(0xffffffffu, v, o));
    int w = threadIdx.x >> 5;
    __syncthreads();
    if ((threadIdx.x & 31) == 0) red[w] = v;
    __syncthreads();
    return fmaxf(fmaxf(red[0], red[1]), fmaxf(red[2], red[3]));
}
__global__ __launch_bounds__(128) void k_grkan2b(
    const float* __restrict__ skip_b,
    const float* __restrict__ gate_ws, const float* __restrict__ gate_bs,
    const float* __restrict__ gate_wv, const float* __restrict__ gate_bv,
    const float* __restrict__ ln_g, const float* __restrict__ ln_b) {
    __shared__ float s_h2[128];
    __shared__ float red[4];
    const int b = blockIdx.x;
    const int u = threadIdx.x;
    s_h2[u] = d_h2g[b * 128 + u];
    __syncthreads();
    float sa = 0.f, va = 0.f;
#pragma unroll 8
    for (int k = 0; k < 128; k++) {
        float h = s_h2[k];
        sa += h * gate_ws[k * 128 + u];
        va += h * gate_wv[k * 128 + u];
    }
    float gate = sigmf(sa + gate_bs[u]) * (va + gate_bv[u]);
    float y = d_skip[b * 128 + u] + skip_b[u] + gate;
    float mu = bsum128(y, red) * (1.f / 128.f);
    float dv = y - mu;
    float var = bsum128(dv * dv, red) * (1.f / 128.f);
    float z = ln_g[u] * dv / sqrtf(var + 1e-3f) + ln_b[u];
    float mx = bmax128(z, red);
    float ez = __expf(z - mx);
    float es = bsum128(ez, red);
    d_wts[b * 128 + u] = ez / es;
}

// ============ K4: final KAN via mma.sync bf16 split precision ============
// 512 blocks, one 128x128 tile each. Warp w -> rows [16w,16w+16), all 128 cols.
// K=576 = 9 chunks of 64 (4 ksteps). A built into fragment-layout smem; B frags
// straight from global (L2-resident). D += AhBh + AhBl + AlBh (fp32 accum).
#define KM_SMEM    (8192 * 4 + 64 * 129 * 4 + 512)
__global__ __launch_bounds__(256, 1) void k_main(const float* __restrict__ x,
                                                 const float* __restrict__ tw,
                                                 float* __restrict__ out) {
    extern __shared__ float smf[];
    uint32_t* Ah = (uint32_t*)smf;                    // [4 sl][8 rt][32 lane][4 regs]
    uint32_t* Al = Ah + 4096;
    float* xt    = smf + 8192;                        // x^T tile [64][129]
    float* wts_s = xt + 64 * 129;
    const int tid = threadIdx.x, w = tid >> 5, lane = tid & 31;
    const int tile = blockIdx.x;
    const size_t row0 = (size_t)tile * 128;

    // stage x tile transposed (coalesced) + softmax weights
    for (int e = tid; e < 2048; e += 256) {
        float4 v = ((const float4*)(x + row0 * 64))[e];
        int r = e >> 4, dd = (e & 15) * 4;
        xt[(dd + 0) * 129 + r] = v.x;
        xt[(dd + 1) * 129 + r] = v.y;
        xt[(dd + 2) * 129 + r] = v.z;
        xt[(dd + 3) * 129 + r] = v.w;
    }
    if (tid < 128) wts_s[tid] = d_wts[(tile >> 3) * 128 + tid];

    float acc[16][4];
#pragma unroll
    for (int f = 0; f < 16; f++)
#pragma unroll
        for (int q = 0; q < 4; q++) acc[f][q] = 0.f;

    for (int c = 0; c < 9; c++) {
        __syncthreads();        // A buffer free (first iter: xt staged)
        // ---- build A chunk into fragment layout ----
        // item: row r (0..127), dl (0..7) covering k-local = dl*8 + nb.
        // A frag: element (row wr, kk) of kstep sl held by lane (wr&7)*4 + (kk&7)/2,
        // reg = (wr<8?0:1) + (kk>=8?2:0), halfword kk&1.
#pragma unroll
        for (int j = 0; j < 4; j++) {
            int it = tid + j * 256;          // 1024 items: [dl 8][r 128]
            int r = it & 127, dl = it >> 7;
            int rt = r >> 4, wr = r & 15, gid = wr & 7;
            int reg = ((wr < 8) ? 0 : 1) + (dl & 1) * 2;
            int slot = (((dl >> 1) * 8 + rt) * 32 + gid * 4) * 4 + reg;
            float t = tw[(row0 + r) & 1023];
            float vals[8];
            if (c == 0) {
#pragma unroll
                for (int nb = 0; nb < 8; nb++)
                    vals[nb] = siluf(t * xt[(dl * 8 + nb) * 129 + r]);
            } else {
                float wv = t * xt[(8 * (c - 1) + dl) * 129 + r];
                bspline8(wv, vals);
            }
#pragma unroll
            for (int pj = 0; pj < 4; pj++) {
                uint32_t h, l;
                split2(vals[2 * pj], vals[2 * pj + 1], h, l);
                Ah[slot + pj * 4] = h;       // lane stride = 4 u32 (FIXED: was pj*16)
                Al[slot + pj * 4] = l;
            }
        }
        __syncthreads();
        // ---- MMA over this chunk's 4 ksteps ----
#pragma unroll
        for (int sl = 0; sl < 4; sl++) {
            const uint4 a_h = ((const uint4*)Ah)[(sl * 8 + w) * 32 + lane];
            const uint4 a_l = ((const uint4*)Al)[(sl * 8 + w) * 32 + lane];
            const uint4* Bp = d_Bfrag + ((c * 4 + sl) * 16) * 32 + lane;
#pragma unroll
            for (int f = 0; f < 16; f++) {
                const uint4 b = Bp[f * 32];
                mma16816(acc[f], a_h.x, a_h.y, a_h.z, a_h.w, b.x, b.y);  // hh
                mma16816(acc[f], a_h.x, a_h.y, a_h.z, a_h.w, b.z, b.w);  // hl
                mma16816(acc[f], a_l.x, a_l.y, a_l.z, a_l.w, b.x, b.y);  // lh
            }
        }
    }
    __syncthreads();

    // ---- epilogue: scale by softmax weights, direct STG.64 ----
    const int rlo = w * 16 + (lane >> 2);
#pragma unroll
    for (int f = 0; f < 16; f++) {
        int c0 = f * 8 + (lane & 3) * 2;
        float w0 = wts_s[c0], w1 = wts_s[c0 + 1];
        float2 v0 = make_float2(acc[f][0] * w0, acc[f][1] * w1);
        float2 v1 = make_float2(acc[f][2] * w0, acc[f][3] * w1);
        *(float2*)(out + (row0 + rlo) * 128 + c0)     = v0;
        *(float2*)(out + (row0 + rlo + 8) * 128 + c0) = v1;
    }
}

extern "C" void kernel_launch(void* const* d_in, const int* in_sizes, int n_in,
                              void* d_out, int out_size) {
    const float* x          = (const float*)d_in[0];
    const float* tw         = (const float*)d_in[1];
    const float* kan_base   = (const float*)d_in[2];
    const float* kan_spline = (const float*)d_in[3];
    const float* g1_base    = (const float*)d_in[4];
    const float* g1_spline  = (const float*)d_in[5];
    const float* g2_base    = (const float*)d_in[6];
    const float* g2_spline  = (const float*)d_in[7];
    const float* skip_w     = (const float*)d_in[8];
    const float* skip_b     = (const float*)d_in[9];
    const float* gate_ws    = (const float*)d_in[10];
    const float* gate_bs    = (const float*)d_in[11];
    const float* gate_wv    = (const float*)d_in[12];
    const float* gate_bv    = (const float*)d_in[13];
    const float* ln_g       = (const float*)d_in[14];
    const float* ln_b       = (const float*)d_in[15];
    float* out = (float*)d_out;

    cudaFuncSetAttribute(k_sig,    cudaFuncAttributeMaxDynamicSharedMemorySize, KSIG_SMEM);
    cudaFuncSetAttribute(k_grkan1, cudaFuncAttributeMaxDynamicSharedMemorySize, K3_SMEM);
    cudaFuncSetAttribute(k_main,   cudaFuncAttributeMaxDynamicSharedMemorySize, KM_SMEM);

    k_init<<<(64 * 4160 + 255) / 256, 256>>>(x, tw);
    k_prep<<<72, 256>>>(kan_base, kan_spline);
    k_sig<<<dim3(64, 8), 256, KSIG_SMEM>>>(x, tw);
    k_grkan1<<<dim3(4, 65), 256, K3_SMEM>>>(g1_base, g1_spline, skip_w);
    k_grkan2a<<<256, 128>>>(g2_base, g2_spline);
    k_grkan2b<<<64, 128>>>(skip_b, gate_ws, gate_bs, gate_wv, gate_bv, ln_g, ln_b);
    k_main<<<512, 256, KM_SMEM>>>(x, tw, out);
}

// round 9
// speedup vs baseline: 2.3163x; 1.0021x over previous
#include <cuda_runtime.h>
#include <cuda_bf16.h>
#include <cstdint>

// B=64, S=1024, D=64, U=128, NB=8, SIG_DIM=4160; final-KAN K = 64+512 = 576
// K = 36 ksteps of 16; N = 128 = 16 n-frags of 8.

__device__ float d_sig[64 * 4160];
__device__ float d_h1[64 * 128];
__device__ float d_h2g[64 * 128];
__device__ float d_skip[64 * 128];
__device__ float d_wts[64 * 128];
// B operand in m16n8k16 fragment layout: [kstep 36][nfrag 16][lane 32] = {bh0,bh1,bl0,bl1}
__device__ uint4 d_Bfrag[36 * 16 * 32];

__device__ __forceinline__ float siluf(float v) { return v / (1.f + __expf(-v)); }
__device__ __forceinline__ float sigmf(float v) { return 1.f / (1.f + __expf(-v)); }

// Cox-de Boor, GRID_SIZE=5, order 3, uniform knots g(k)=0.4k-2.2 -> 8 bases
__device__ __forceinline__ void bspline8(float x, float* o) {
    float bb[11];
#pragma unroll
    for (int k = 0; k < 11; k++) {
        float gk = 0.4f * k - 2.2f, gk1 = 0.4f * (k + 1) - 2.2f;
        bb[k] = (x >= gk && x < gk1) ? 1.f : 0.f;
    }
#pragma unroll
    for (int p = 1; p <= 3; p++) {
        float inv = 1.f / (0.4f * p);
#pragma unroll
        for (int k = 0; k + p < 11; k++) {
            float gk = 0.4f * k - 2.2f, gkp1 = 0.4f * (k + p + 1) - 2.2f;
            bb[k] = (x - gk) * inv * bb[k] + (gkp1 - x) * inv * bb[k + 1];
        }
    }
#pragma unroll
    for (int k = 0; k < 8; k++) o[k] = bb[k];
}

__device__ __forceinline__ void ffma2(unsigned long long& d, unsigned long long a,
                                      unsigned long long b) {
    asm("fma.rn.f32x2 %0, %1, %2, %0;" : "+l"(d) : "l"(a), "l"(b));
}
__device__ __forceinline__ unsigned long long bcast2(float v) {
    unsigned long long r; unsigned int u = __float_as_uint(v);
    asm("mov.b64 %0, {%1, %1};" : "=l"(r) : "r"(u));
    return r;
}
__device__ __forceinline__ float2 unpack2(unsigned long long v) {
    unsigned int lo, hi;
    asm("mov.b64 {%0, %1}, %2;" : "=r"(lo), "=r"(hi) : "l"(v));
    return make_float2(__uint_as_float(lo), __uint_as_float(hi));
}
// split fp32 pair -> packed bf16 hi pair + bf16 lo (residual) pair
__device__ __forceinline__ void split2(float a, float b, uint32_t& h, uint32_t& l) {
    __nv_bfloat16 ah = __float2bfloat16(a), bh = __float2bfloat16(b);
    __nv_bfloat16 al = __float2bfloat16(a - __bfloat162float(ah));
    __nv_bfloat16 bl = __float2bfloat16(b - __bfloat162float(bh));
    h = (uint32_t)__bfloat16_as_ushort(ah) | ((uint32_t)__bfloat16_as_ushort(bh) << 16);
    l = (uint32_t)__bfloat16_as_ushort(al) | ((uint32_t)__bfloat16_as_ushort(bl) << 16);
}
// m16n8k16 row.col bf16 MMA, fp32 accumulate in place
__device__ __forceinline__ void mma16816(float* d, uint32_t a0, uint32_t a1, uint32_t a2,
                                         uint32_t a3, uint32_t b0, uint32_t b1) {
    asm("mma.sync.aligned.m16n8k16.row.col.f32.bf16.bf16.f32 "
        "{%0,%1,%2,%3}, {%4,%5,%6,%7}, {%8,%9}, {%0,%1,%2,%3};"
        : "+f"(d[0]), "+f"(d[1]), "+f"(d[2]), "+f"(d[3])
        : "r"(a0), "r"(a1), "r"(a2), "r"(a3), "r"(b0), "r"(b1));
}

// ============ K0: init ============
__global__ void k_init(const float* __restrict__ x, const float* __restrict__ tw) {
    int idx = blockIdx.x * blockDim.x + threadIdx.x;
    if (idx < 64 * 4160) {
        int b = idx / 4160, r = idx - b * 4160;
        if (r < 64) {
            float wl = tw[1023] * x[((size_t)b * 1024 + 1023) * 64 + r];
            float w0 = tw[0]    * x[(size_t)b * 1024 * 64 + r];
            d_sig[idx] = wl - w0;
        } else d_sig[idx] = 0.f;
    }
    if (idx < 64 * 128) { d_h1[idx] = 0.f; d_skip[idx] = 0.f; d_h2g[idx] = 0.f; }
}

// ============ K-prep: W^T (576x128) -> bf16 hi/lo m16n8k16 B-fragment layout ======
__global__ void k_prep(const float* __restrict__ kan_base,
                       const float* __restrict__ kan_spline) {
    int idx = blockIdx.x * blockDim.x + threadIdx.x;
    if (idx >= 36 * 16 * 32) return;
    int l = idx & 31, f = (idx >> 5) & 15, s = idx >> 9;
    int n = f * 8 + (l >> 2);
    int k0 = s * 16 + (l & 3) * 2;
    float w[4];
#pragma unroll
    for (int q = 0; q < 4; q++) {
        int k = k0 + (q >> 1) * 8 + (q & 1);
        w[q] = (k < 64) ? kan_base[k * 128 + n] : kan_spline[(size_t)(k - 64) * 128 + n];
    }
    uint4 v;
    split2(w[0], w[1], v.x, v.z);
    split2(w[2], w[3], v.y, v.w);
    d_Bfrag[idx] = v;
}

// ============ K1: level-2 signature (unchanged) ============
#define KSIG_SMEM (2 * 128 * 64 * 4)
__global__ __launch_bounds__(256) void k_sig(const float* __restrict__ x,
                                             const float* __restrict__ tw) {
    extern __shared__ float sm[];
    float* sM = sm; float* sU = sm + 128 * 64;
    const int b = blockIdx.x, chunk = blockIdx.y, t0 = chunk * 128;
    const int steps = (chunk == 7) ? 127 : 128;
    const int tid = threadIdx.x;
    const size_t xb = (size_t)b * 1024 * 64;
    for (int e = tid; e < steps * 64; e += 256) {
        int t = e >> 6, d = e & 63;
        float wt0 = tw[t0 + t]     * x[xb + (size_t)(t0 + t) * 64 + d];
        float wt1 = tw[t0 + t + 1] * x[xb + (size_t)(t0 + t + 1) * 64 + d];
        float w0v = tw[0] * x[xb + d];
        sU[t * 64 + d] = wt1 - wt0;
        sM[t * 64 + d] = 0.5f * (wt0 + wt1) - w0v;
    }
    __syncthreads();
    const int jp = tid & 31, i0 = (tid >> 5) * 8;
    unsigned long long acc[8];
#pragma unroll
    for (int q = 0; q < 8; q++) acc[q] = 0ull;
#pragma unroll 2
    for (int t = 0; t < steps; t++) {
        const float4 m0 = *reinterpret_cast<const float4*>(&sM[t * 64 + i0]);
        const float4 m1 = *reinterpret_cast<const float4*>(&sM[t * 64 + i0 + 4]);
        const unsigned long long u2 =
            *reinterpret_cast<const unsigned long long*>(&sU[t * 64 + 2 * jp]);
        ffma2(acc[0], u2, bcast2(m0.x)); ffma2(acc[1], u2, bcast2(m0.y));
        ffma2(acc[2], u2, bcast2(m0.z)); ffma2(acc[3], u2, bcast2(m0.w));
        ffma2(acc[4], u2, bcast2(m1.x)); ffma2(acc[5], u2, bcast2(m1.y));
        ffma2(acc[6], u2, bcast2(m1.z)); ffma2(acc[7], u2, bcast2(m1.w));
    }
#pragma unroll
    for (int q = 0; q < 8; q++) {
        float2 f = unpack2(acc[q]);
        int i = i0 + q;
        atomicAdd(&d_sig[b * 4160 + 64 + i * 64 + 2 * jp],     f.x);
        atomicAdd(&d_sig[b * 4160 + 64 + i * 64 + 2 * jp + 1], f.y);
    }
}

// ============ K2: GRKAN layer 1 (h1) + skip — occupancy-fixed ============
// Batch tile 16 (was 64): smem 160KB -> 40KB, 2 rows/thread (was 8) -> ~4 CTAs/SM.
// Grid (4 col-tiles, 65 k-chunks, 4 batch-tiles). Weights stream via L1/L2
// (19MB fits L2; extra re-reads across batch tiles are L2 hits).
#define K3_SMEM ((1024 + 1024 + 8192) * 4)
__global__ __launch_bounds__(256) void k_grkan1(const float* __restrict__ g1_base,
                                                const float* __restrict__ g1_spline,
                                                const float* __restrict__ skip_w) {
    extern __shared__ float sm[];
    float* s_sig = sm;           // [16 b][64 d]
    float* s_sil = sm + 1024;
    float* s_bas = sm + 2048;    // [16][64][8]
    const int ct = blockIdx.x, kc = blockIdx.y, bt = blockIdx.z;
    const int d0 = kc * 64;
    const int tid = threadIdx.x;
    for (int e = tid; e < 1024; e += 256) {
        int bidx = e >> 6, dl = e & 63;
        float v = d_sig[(bt * 16 + bidx) * 4160 + d0 + dl];
        s_sig[e] = v; s_sil[e] = siluf(v);
        bspline8(v, &s_bas[e * 8]);
    }
    __syncthreads();
    const int col = ct * 32 + (tid & 31);
    const int ty  = tid >> 5;          // warp id -> batches ty*2, ty*2+1
    float acc_h0 = 0.f, acc_h1 = 0.f, acc_s0 = 0.f, acc_s1 = 0.f;
#pragma unroll 2
    for (int dl = 0; dl < 64; dl++) {
        const int d = d0 + dl;
        float wb = g1_base[d * 128 + col];
        float wk = skip_w[d * 128 + col];
        float ws[8];
#pragma unroll
        for (int nb = 0; nb < 8; nb++) ws[nb] = g1_spline[((size_t)d * 8 + nb) * 128 + col];
        const int b0 = ty * 2, b1 = ty * 2 + 1;
        const float* bp0 = &s_bas[(b0 * 64 + dl) * 8];
        const float* bp1 = &s_bas[(b1 * 64 + dl) * 8];
        float h0 = s_sil[b0 * 64 + dl] * wb;
        float h1 = s_sil[b1 * 64 + dl] * wb;
#pragma unroll
        for (int nb = 0; nb < 8; nb++) { h0 += bp0[nb] * ws[nb]; h1 += bp1[nb] * ws[nb]; }
        acc_h0 += h0; acc_h1 += h1;
        acc_s0 += s_sig[b0 * 64 + dl] * wk;
        acc_s1 += s_sig[b1 * 64 + dl] * wk;
    }
    const int gb0 = bt * 16 + ty * 2, gb1 = gb0 + 1;
    atomicAdd(&d_h1[gb0 * 128 + col], acc_h0);
    atomicAdd(&d_h1[gb1 * 128 + col], acc_h1);
    atomicAdd(&d_skip[gb0 * 128 + col], acc_s0);
    atomicAdd(&d_skip[gb1 * 128 + col], acc_s1);
}

// ============ K3a: h2 = kan_linear(h1, g2), split-K x4, 256 blocks ============
__global__ __launch_bounds__(128) void k_grkan2a(const float* __restrict__ g2_base,
                                                 const float* __restrict__ g2_spline) {
    __shared__ float s_sil[32];
    __shared__ float s_bas[32][8];
    const int b = blockIdx.x >> 2, kq = blockIdx.x & 3;
    const int u = threadIdx.x;
    const int k0 = kq * 32;
    if (u < 32) {
        float v = d_h1[b * 128 + k0 + u];
        s_sil[u] = siluf(v);
        bspline8(v, &s_bas[u][0]);
    }
    __syncthreads();
    float acc = 0.f;
#pragma unroll 8
    for (int kk = 0; kk < 32; kk++) {
        int k = k0 + kk;
        float h = s_sil[kk] * g2_base[k * 128 + u];
#pragma unroll
        for (int nb = 0; nb < 8; nb++)
            h += s_bas[kk][nb] * g2_spline[((size_t)k * 8 + nb) * 128 + u];
        acc += h;
    }
    atomicAdd(&d_h2g[b * 128 + u], acc);
}

// ============ K3b: gate + layernorm + softmax -> d_wts (64 blocks x 128) ============
__device__ __forceinline__ float bsum128(float v, volatile float* red) {
#pragma unroll
    for (int o = 16; o > 0; o >>= 1) v += __shfl_xor_sync(0xffffffffu, v, o);
    int w = threadIdx.x >> 5;
    __syncthreads();
    if ((threadIdx.x & 31) == 0) red[w] = v;
    __syncthreads();
    return red[0] + red[1] + red[2] + red[3];
}
__device__ __forceinline__ float bmax128(float v, volatile float* red) {
#pragma unroll
    for (int o = 16; o > 0; o >>= 1) v = fmaxf(v, __shfl_xor_sync(0xffffffffu, v, o));
    int w = threadIdx.x >> 5;
    __syncthreads();
    if ((threadIdx.x & 31) == 0) red[w] = v;
    __syncthreads();
    return fmaxf(fmaxf(red[0], red[1]), fmaxf(red[2], red[3]));
}
__global__ __launch_bounds__(128) void k_grkan2b(
    const float* __restrict__ skip_b,
    const float* __restrict__ gate_ws, const float* __restrict__ gate_bs,
    const float* __restrict__ gate_wv, const float* __restrict__ gate_bv,
    const float* __restrict__ ln_g, const float* __restrict__ ln_b) {
    __shared__ float s_h2[128];
    __shared__ float red[4];
    const int b = blockIdx.x;
    const int u = threadIdx.x;
    s_h2[u] = d_h2g[b * 128 + u];
    __syncthreads();
    float sa = 0.f, va = 0.f;
#pragma unroll 8
    for (int k = 0; k < 128; k++) {
        float h = s_h2[k];
        sa += h * gate_ws[k * 128 + u];
        va += h * gate_wv[k * 128 + u];
    }
    float gate = sigmf(sa + gate_bs[u]) * (va + gate_bv[u]);
    float y = d_skip[b * 128 + u] + skip_b[u] + gate;
    float mu = bsum128(y, red) * (1.f / 128.f);
    float dv = y - mu;
    float var = bsum128(dv * dv, red) * (1.f / 128.f);
    float z = ln_g[u] * dv / sqrtf(var + 1e-3f) + ln_b[u];
    float mx = bmax128(z, red);
    float ez = __expf(z - mx);
    float es = bsum128(ez, red);
    d_wts[b * 128 + u] = ez / es;
}

// ============ K4: final KAN via mma.sync bf16 split precision (unchanged) ============
#define KM_SMEM    (8192 * 4 + 64 * 129 * 4 + 512)
__global__ __launch_bounds__(256, 1) void k_main(const float* __restrict__ x,
                                                 const float* __restrict__ tw,
                                                 float* __restrict__ out) {
    extern __shared__ float smf[];
    uint32_t* Ah = (uint32_t*)smf;                    // [4 sl][8 rt][32 lane][4 regs]
    uint32_t* Al = Ah + 4096;
    float* xt    = smf + 8192;                        // x^T tile [64][129]
    float* wts_s = xt + 64 * 129;
    const int tid = threadIdx.x, w = tid >> 5, lane = tid & 31;
    const int tile = blockIdx.x;
    const size_t row0 = (size_t)tile * 128;

    for (int e = tid; e < 2048; e += 256) {
        float4 v = ((const float4*)(x + row0 * 64))[e];
        int r = e >> 4, dd = (e & 15) * 4;
        xt[(dd + 0) * 129 + r] = v.x;
        xt[(dd + 1) * 129 + r] = v.y;
        xt[(dd + 2) * 129 + r] = v.z;
        xt[(dd + 3) * 129 + r] = v.w;
    }
    if (tid < 128) wts_s[tid] = d_wts[(tile >> 3) * 128 + tid];

    float acc[16][4];
#pragma unroll
    for (int f = 0; f < 16; f++)
#pragma unroll
        for (int q = 0; q < 4; q++) acc[f][q] = 0.f;

    for (int c = 0; c < 9; c++) {
        __syncthreads();
#pragma unroll
        for (int j = 0; j < 4; j++) {
            int it = tid + j * 256;          // 1024 items: [dl 8][r 128]
            int r = it & 127, dl = it >> 7;
            int rt = r >> 4, wr = r & 15, gid = wr & 7;
            int reg = ((wr < 8) ? 0 : 1) + (dl & 1) * 2;
            int slot = (((dl >> 1) * 8 + rt) * 32 + gid * 4) * 4 + reg;
            float t = tw[(row0 + r) & 1023];
            float vals[8];
            if (c == 0) {
#pragma unroll
                for (int nb = 0; nb < 8; nb++)
                    vals[nb] = siluf(t * xt[(dl * 8 + nb) * 129 + r]);
            } else {
                float wv = t * xt[(8 * (c - 1) + dl) * 129 + r];
                bspline8(wv, vals);
            }
#pragma unroll
            for (int pj = 0; pj < 4; pj++) {
                uint32_t h, l;
                split2(vals[2 * pj], vals[2 * pj + 1], h, l);
                Ah[slot + pj * 4] = h;
                Al[slot + pj * 4] = l;
            }
        }
        __syncthreads();
#pragma unroll
        for (int sl = 0; sl < 4; sl++) {
            const uint4 a_h = ((const uint4*)Ah)[(sl * 8 + w) * 32 + lane];
            const uint4 a_l = ((const uint4*)Al)[(sl * 8 + w) * 32 + lane];
            const uint4* Bp = d_Bfrag + ((c * 4 + sl) * 16) * 32 + lane;
#pragma unroll
            for (int f = 0; f < 16; f++) {
                const uint4 b = Bp[f * 32];
                mma16816(acc[f], a_h.x, a_h.y, a_h.z, a_h.w, b.x, b.y);  // hh
                mma16816(acc[f], a_h.x, a_h.y, a_h.z, a_h.w, b.z, b.w);  // hl
                mma16816(acc[f], a_l.x, a_l.y, a_l.z, a_l.w, b.x, b.y);  // lh
            }
        }
    }
    __syncthreads();

    const int rlo = w * 16 + (lane >> 2);
#pragma unroll
    for (int f = 0; f < 16; f++) {
        int c0 = f * 8 + (lane & 3) * 2;
        float w0 = wts_s[c0], w1 = wts_s[c0 + 1];
        float2 v0 = make_float2(acc[f][0] * w0, acc[f][1] * w1);
        float2 v1 = make_float2(acc[f][2] * w0, acc[f][3] * w1);
        *(float2*)(out + (row0 + rlo) * 128 + c0)     = v0;
        *(float2*)(out + (row0 + rlo + 8) * 128 + c0) = v1;
    }
}

extern "C" void kernel_launch(void* const* d_in, const int* in_sizes, int n_in,
                              void* d_out, int out_size) {
    const float* x          = (const float*)d_in[0];
    const float* tw         = (const float*)d_in[1];
    const float* kan_base   = (const float*)d_in[2];
    const float* kan_spline = (const float*)d_in[3];
    const float* g1_base    = (const float*)d_in[4];
    const float* g1_spline  = (const float*)d_in[5];
    const float* g2_base    = (const float*)d_in[6];
    const float* g2_spline  = (const float*)d_in[7];
    const float* skip_w     = (const float*)d_in[8];
    const float* skip_b     = (const float*)d_in[9];
    const float* gate_ws    = (const float*)d_in[10];
    const float* gate_bs    = (const float*)d_in[11];
    const float* gate_wv    = (const float*)d_in[12];
    const float* gate_bv    = (const float*)d_in[13];
    const float* ln_g       = (const float*)d_in[14];
    const float* ln_b       = (const float*)d_in[15];
    float* out = (float*)d_out;

    cudaFuncSetAttribute(k_sig,    cudaFuncAttributeMaxDynamicSharedMemorySize, KSIG_SMEM);
    cudaFuncSetAttribute(k_grkan1, cudaFuncAttributeMaxDynamicSharedMemorySize, K3_SMEM);
    cudaFuncSetAttribute(k_main,   cudaFuncAttributeMaxDynamicSharedMemorySize, KM_SMEM);

    k_init<<<(64 * 4160 + 255) / 256, 256>>>(x, tw);
    k_prep<<<72, 256>>>(kan_base, kan_spline);
    k_sig<<<dim3(64, 8), 256, KSIG_SMEM>>>(x, tw);
    k_grkan1<<<dim3(4, 65, 4), 256, K3_SMEM>>>(g1_base, g1_spline, skip_w);
    k_grkan2a<<<256, 128>>>(g2_base, g2_spline);
    k_grkan2b<<<64, 128>>>(skip_b, gate_ws, gate_bs, gate_wv, gate_bv, ln_g, ln_b);
    k_main<<<512, 256, KM_SMEM>>>(x, tw, out);
}